// round 12
// baseline (speedup 1.0000x reference)
#include <cuda_runtime.h>
#include <cuda_fp16.h>
#include <cstdint>

// ============================================================================
// VectorQuantizerEMA — persistent 2-CTA/SM HMMA, single-pass fp16 scoring,
// streamed packed-key argmax (spill-free), candidate-pruned exact recheck.
// ============================================================================

#define NC      512
#define CD      64
#define NROWS   (64 * 4096)
#define NELEM   (NROWS * CD)
#define TROWS   64
#define NTILES  (NROWS / TROWS)     // 4096
#define GRID    296                 // 2 CTAs per SM
#define TAU     0.20f

#define O_ZQ    ((size_t)0)
#define O_LOSS  ((size_t)16777216)
#define O_IDX   ((size_t)16777217)
#define O_NEMB  ((size_t)17039361)
#define O_NCS   ((size_t)17072129)
#define O_NAVG  ((size_t)17072641)

// ---- device scratch --------------------------------------------------------
__device__ __align__(16) float g_esum[NC * CD];
__device__ __align__(16) unsigned short g_Bh16[NC * CD];  // fp16 E row-major
__device__ float g_counts[NC];
__device__ float g_h[NC];            // 0.5*||e||^2
__device__ float g_sse;

// ---- smem layout (bytes, per CTA) ------------------------------------------
#define SM_Z0    0        // 16KB raw z tile buf A
#define SM_Z1    16384    // 16KB raw z tile buf B
#define SM_AH    32768    // 8KB fp16 A, swizzled
#define SM_R2    40960    // 4KB uint2 (key1,key2) per (row,warp)  64x8
#define SM_H     45056    // 2KB
#define SM_CNT   47104    // 2KB
#define SM_BI    49152    // 256B
#define SM_BEST  49408    // 256B
#define SM_LIST  49664    // 256B
#define SM_FLG   49920    // 64B
#define SM_NFLG  49984
#define SMEM_SZ  50048

__device__ __forceinline__ uint32_t smem_u32(const void* p) {
    uint32_t a;
    asm("{ .reg .u64 t; cvta.to.shared.u64 t, %1; cvt.u32.u64 %0, t; }" : "=r"(a) : "l"(p));
    return a;
}
__device__ __forceinline__ void ldsm_x4(uint32_t a, uint32_t* r) {
    asm volatile("ldmatrix.sync.aligned.m8n8.x4.shared.b16 {%0,%1,%2,%3}, [%4];"
        : "=r"(r[0]), "=r"(r[1]), "=r"(r[2]), "=r"(r[3]) : "r"(a));
}
__device__ __forceinline__ void mma16816(float* c, const uint32_t* a, const uint32_t* b) {
    asm volatile("mma.sync.aligned.m16n8k16.row.col.f32.f16.f16.f32 "
        "{%0,%1,%2,%3}, {%4,%5,%6,%7}, {%8,%9}, {%0,%1,%2,%3};"
        : "+f"(c[0]), "+f"(c[1]), "+f"(c[2]), "+f"(c[3])
        : "r"(a[0]), "r"(a[1]), "r"(a[2]), "r"(a[3]), "r"(b[0]), "r"(b[1]));
}
__device__ __forceinline__ uint32_t packh(float x, float y) {
    __half2 h = __floats2half2_rn(x, y);
    return *(uint32_t*)&h;
}
__device__ __forceinline__ void cp16(uint32_t d, const void* s) {
    asm volatile("cp.async.cg.shared.global [%0], [%1], 16;" :: "r"(d), "l"(s));
}
#define CP_COMMIT() asm volatile("cp.async.commit_group;")
#define CP_WAIT0()  asm volatile("cp.async.wait_group 0;")

// ---- packed monotonic keys -------------------------------------------------
__device__ __forceinline__ uint32_t mkkey(float s, int j) {
    uint32_t u = __float_as_uint(s);
    u ^= (uint32_t)((int32_t)u >> 31) | 0x80000000u;
    return (u & 0xFFFFFE00u) | (uint32_t)(511 - j);
}
__device__ __forceinline__ float dkey(uint32_t k) {
    uint32_t u = k & 0xFFFFFE00u;
    u = (u & 0x80000000u) ? (u ^ 0x80000000u) : ~u;
    return __uint_as_float(u);
}
__device__ __forceinline__ uint32_t umaxu(uint32_t a, uint32_t b) { return a > b ? a : b; }
__device__ __forceinline__ uint32_t uminu(uint32_t a, uint32_t b) { return a < b ? a : b; }
// merge running (m1,m2) with sorted pair (hi,lo)
__device__ __forceinline__ void pmerge(uint32_t& m1, uint32_t& m2,
                                       uint32_t hi, uint32_t lo) {
    m2 = umaxu(umaxu(m2, lo), uminu(m1, hi));
    m1 = umaxu(m1, hi);
}

__device__ __forceinline__ float exact_score(const float4* __restrict__ f,
                                             const float* __restrict__ emb,
                                             const float* __restrict__ sH, int j) {
    const float4* er = (const float4*)(emb + (size_t)j * CD);
    float acc = 0.0f;
#pragma unroll
    for (int i = 0; i < 16; i++) {
        float4 e = er[i];
        acc += f[i].x * e.x + f[i].y * e.y + f[i].z * e.z + f[i].w * e.w;
    }
    return acc - sH[j];
}

// ============================================================================
// Kernel 1: zero scratch, half-norms, fp16 B
// ============================================================================
__global__ void vq_init(const float* __restrict__ emb) {
    int t = blockIdx.x * blockDim.x + threadIdx.x;   // 32768
    if (t < NC * CD) {
        g_esum[t] = 0.0f;
        g_Bh16[t] = __half_as_ushort(__float2half_rn(emb[t]));
    }
    if (t == 0) g_sse = 0.0f;
    if (t < NC) {
        g_counts[t] = 0.0f;
        const float4* e = (const float4*)(emb + (size_t)t * CD);
        float s = 0.0f;
#pragma unroll
        for (int i = 0; i < CD / 4; i++) {
            float4 v = e[i];
            s += v.x * v.x + v.y * v.y + v.z * v.z + v.w * v.w;
        }
        g_h[t] = 0.5f * s;
    }
}

// no-op spacers so ncu -s 5 lands on vq_main
__global__ void vq_nop1() {}
__global__ void vq_nop2() {}

// ============================================================================
// Kernel 2: persistent main. 296 CTAs x 256 thr (8 warps), 64-row tiles.
// ============================================================================
__global__ void __launch_bounds__(256, 2)
vq_main(const float* __restrict__ z, const float* __restrict__ emb,
        float* __restrict__ out) {
    extern __shared__ __align__(16) char smem[];
    const uint32_t sb32 = smem_u32(smem);
    float*  sH   = (float*)(smem + SM_H);
    float*  sCnt = (float*)(smem + SM_CNT);
    int*    sBI  = (int*)(smem + SM_BI);
    float*  sBest= (float*)(smem + SM_BEST);
    int*    sLst = (int*)(smem + SM_LIST);
    unsigned char* sFlg = (unsigned char*)(smem + SM_FLG);
    int*    sNF  = (int*)(smem + SM_NFLG);
    uint2*  sR2  = (uint2*)(smem + SM_R2);

    const int tid  = threadIdx.x;
    const int wid  = tid >> 5;      // 0..7
    const int lane = tid & 31;

    // ---- prologue: prefetch first tile; stage h; zero counters ----
    {
        uint32_t dst = sb32 + SM_Z0;
        const char* src = (const char*)(z + (size_t)blockIdx.x * TROWS * CD);
#pragma unroll
        for (int i = 0; i < 4; i++) {
            int c = tid + i * 256;
            cp16(dst + c * 16, src + c * 16);
        }
        CP_COMMIT();
    }
#pragma unroll
    for (int i = 0; i < 2; i++) {
        sH[tid + 256 * i] = g_h[tid + 256 * i];
        sCnt[tid + 256 * i] = 0.0f;
    }

    const int jw = wid * 64;
    // ---- hoist B fragments once: 8 nt x 4 ks x {b0,b1} = 64 regs ----
    uint32_t Breg[8][4][2];
#pragma unroll
    for (int nt = 0; nt < 8; nt++) {
        int code = jw + nt * 8 + (lane >> 2);
        const uint32_t* row = (const uint32_t*)(g_Bh16 + (size_t)code * CD);
#pragma unroll
        for (int ks = 0; ks < 4; ks++) {
            int k2 = ks * 8 + (lane & 3);
            Breg[nt][ks][0] = row[k2];
            Breg[nt][ks][1] = row[k2 + 4];
        }
    }
    __syncthreads();

    // half-norms packed fp16x2 per (h,n4): 8 regs instead of 16
    __half2 hreg2[8];
#pragma unroll
    for (int h = 0; h < 2; h++)
#pragma unroll
        for (int n4 = 0; n4 < 4; n4++) {
            int j0 = jw + h * 32 + n4 * 8 + 2 * (lane & 3);
            hreg2[h * 4 + n4] = __floats2half2_rn(sH[j0], sH[j0 + 1]);
        }

    const int myrow = tid >> 2;          // 0..63
    const int myq   = tid & 3;

    float sse_acc = 0.0f;
    int it = 0;
#pragma unroll 1
    for (int tile = blockIdx.x; tile < NTILES; tile += GRID, it++) {
        const uint32_t zoff = (it & 1) ? SM_Z1 : SM_Z0;

        CP_WAIT0();
        __syncthreads();                 // cur z resident; prev phases done

        // ---- convert: z quarter -> fp16 AH (swizzled) ----
        {
            const float4* zr = (const float4*)(smem + zoff + myrow * 256 + myq * 64);
            float4 v0 = zr[0], v1 = zr[1], v2 = zr[2], v3 = zr[3];
            uint4 H0, H1;
            H0.x = packh(v0.x, v0.y); H0.y = packh(v0.z, v0.w);
            H0.z = packh(v1.x, v1.y); H0.w = packh(v1.z, v1.w);
            H1.x = packh(v2.x, v2.y); H1.y = packh(v2.z, v2.w);
            H1.z = packh(v3.x, v3.y); H1.w = packh(v3.z, v3.w);
            uint4* pH = (uint4*)(smem + SM_AH + myrow * 128);
            pH[(2 * myq) ^ (myrow & 7)]     = H0;
            pH[(2 * myq + 1) ^ (myrow & 7)] = H1;
        }
        if (tid == 0) *sNF = 0;
        __syncthreads();

        // ---- prefetch next tile into other buffer (overlaps MMA) ----
        {
            int tn = tile + GRID;
            if (tn < NTILES) {
                uint32_t dst = sb32 + ((it & 1) ? SM_Z0 : SM_Z1);
                const char* src = (const char*)(z + (size_t)tn * TROWS * CD);
#pragma unroll
                for (int i = 0; i < 4; i++) {
                    int c = tid + i * 256;
                    cp16(dst + c * 16, src + c * 16);
                }
            }
            CP_COMMIT();
        }

        // ---- MMA mainloop: 4 row-tiles x two 4-nt halves; streamed keys ----
#pragma unroll 1
        for (int rt = 0; rt < 4; rt++) {
            uint32_t Ah[16];
            {
                int rl = 16 * rt + (lane & 7) + (((lane >> 3) & 1) << 3);
                int ch = (lane >> 4) & 1;
                uint32_t baseH = sb32 + SM_AH + rl * 128;
                int sw = rl & 7;
#pragma unroll
                for (int ks = 0; ks < 4; ks++)
                    ldsm_x4(baseH + (((2 * ks + ch) ^ sw) << 4), &Ah[ks * 4]);
            }
            uint32_t a1 = 0, a2 = 0, b1 = 0, b2 = 0;   // running top-2 keys
#pragma unroll
            for (int h = 0; h < 2; h++) {
                float C[16];
#pragma unroll
                for (int i = 0; i < 16; i++) C[i] = 0.0f;
#pragma unroll
                for (int n4 = 0; n4 < 4; n4++)
#pragma unroll
                    for (int ks = 0; ks < 4; ks++)
                        mma16816(&C[n4 * 4], &Ah[ks * 4], Breg[h * 4 + n4][ks]);

#pragma unroll
                for (int n4 = 0; n4 < 4; n4++) {
                    float2 hh = __half22float2(hreg2[h * 4 + n4]);
                    int j0 = jw + h * 32 + n4 * 8 + 2 * (lane & 3);
                    uint32_t k0 = mkkey(C[n4 * 4 + 0] - hh.x, j0);
                    uint32_t k1 = mkkey(C[n4 * 4 + 1] - hh.y, j0 + 1);
                    uint32_t hi = umaxu(k0, k1), lo = uminu(k0, k1);
                    if (h == 0 && n4 == 0) { a1 = hi; a2 = lo; }
                    else                   pmerge(a1, a2, hi, lo);
                    k0 = mkkey(C[n4 * 4 + 2] - hh.x, j0);
                    k1 = mkkey(C[n4 * 4 + 3] - hh.y, j0 + 1);
                    hi = umaxu(k0, k1); lo = uminu(k0, k1);
                    if (h == 0 && n4 == 0) { b1 = hi; b2 = lo; }
                    else                   pmerge(b1, b2, hi, lo);
                }
            }
            // cross-lane top-2 over the 4 lanes sharing each row
#pragma unroll
            for (int m = 1; m <= 2; m <<= 1) {
                uint32_t o1 = __shfl_xor_sync(0xffffffffu, a1, m);
                uint32_t o2 = __shfl_xor_sync(0xffffffffu, a2, m);
                pmerge(a1, a2, umaxu(o1, o2), uminu(o1, o2));
                o1 = __shfl_xor_sync(0xffffffffu, b1, m);
                o2 = __shfl_xor_sync(0xffffffffu, b2, m);
                pmerge(b1, b2, umaxu(o1, o2), uminu(o1, o2));
            }
            if ((lane & 3) == 0) {
                int g = lane >> 2;
                sR2[(16 * rt + g) * 8 + wid]     = make_uint2(a1, a2);
                sR2[(16 * rt + g + 8) * 8 + wid] = make_uint2(b1, b2);
            }
        }
        __syncthreads();

        // ---- per-row combine: 2 threads/row (warps 0-3), then 1 shfl ----
        if (tid < 128) {
            int row = tid >> 1, half = tid & 1;
            uint2 v0 = sR2[row * 8 + half * 4];
            uint32_t m1 = v0.x, m2 = v0.y;
#pragma unroll
            for (int w = 1; w < 4; w++) {
                uint2 v = sR2[row * 8 + half * 4 + w];
                pmerge(m1, m2, v.x, v.y);
            }
            uint32_t o1 = __shfl_xor_sync(0xffffffffu, m1, 1);
            uint32_t o2 = __shfl_xor_sync(0xffffffffu, m2, 1);
            pmerge(m1, m2, o1, o2);
            if (half == 0) {
                float f1 = dkey(m1), f2 = dkey(m2);
                sBI[row] = 511 - (int)(m1 & 0x1FFu);
                sBest[row] = f1;
                int flag = (f1 - f2 < TAU) ? 1 : 0;
                sFlg[row] = (unsigned char)flag;
                if (flag) {
                    int p = atomicAdd(sNF, 1);
                    sLst[p] = row;
                }
            }
        }
        __syncthreads();
        const int nflag = *sNF;
        const bool mine_flagged = sFlg[myrow] != 0;

        // ---- epilogue helper (z from smem zoff) ----
        auto do_epilogue = [&](int bi) {
            size_t rg = (size_t)tile * TROWS + myrow;
            if (myq == 0) {
                out[O_IDX + rg] = (float)bi;
                atomicAdd(&sCnt[bi], 1.0f);
            }
            const float4* er = (const float4*)(emb + (size_t)bi * CD + myq * 16);
            const float4* zr = (const float4*)(smem + zoff + myrow * 256 + myq * 64);
            float4* oq = (float4*)(out + O_ZQ + rg * CD + myq * 16);
            float* es = g_esum + (size_t)bi * CD + myq * 16;
#pragma unroll
            for (int i = 0; i < 4; i++) {
                float4 e = er[i], zf = zr[i];
                float d0 = e.x - zf.x, d1 = e.y - zf.y;
                float d2 = e.z - zf.z, d3 = e.w - zf.w;
                sse_acc += d0 * d0 + d1 * d1 + d2 * d2 + d3 * d3;
                oq[i] = make_float4(zf.x + d0, zf.y + d1, zf.z + d2, zf.w + d3);
                asm volatile("red.global.add.v4.f32 [%0], {%1,%2,%3,%4};"
                    :: "l"(es + i * 4), "f"(zf.x), "f"(zf.y), "f"(zf.z), "f"(zf.w)
                    : "memory");
            }
        };

        // ---- epilogue for unflagged rows (overlaps recheck below) ----
        if (!mine_flagged) do_epilogue(sBI[myrow]);

        // ---- candidate-pruned exact recheck for flagged rows ----
        if (nflag > 0) {
#pragma unroll 1
            for (int li = wid; li < nflag; li += 8) {
                int rowl = sLst[li];
                float thr = sBest[rowl] - TAU;
                float wb = -3.4e38f, wb2 = -3.4e38f; int wic = 0;
                if (lane < 8) {
                    uint2 v = sR2[rowl * 8 + lane];
                    wb = dkey(v.x); wb2 = dkey(v.y);
                    wic = 511 - (int)(v.x & 0x1FFu);
                }
                unsigned candm  = __ballot_sync(0xffffffffu, wb  >= thr);
                unsigned heavym = __ballot_sync(0xffffffffu, wb  >= thr && wb2 >= thr);
                unsigned lightm = candm & ~heavym;

                float4 f[16];
                {
                    const float4* zr = (const float4*)(smem + zoff + rowl * 256);
#pragma unroll
                    for (int i = 0; i < 16; i++) f[i] = zr[i];
                }
                float lb = -3.4e38f; int lj = NC;
                if (lightm & (1u << lane)) {
                    lb = exact_score(f, emb, sH, wic);
                    lj = wic;
                }
#pragma unroll 1
                while (heavym) {       // heavy block = 64 codes -> 2 scans
                    int c = __ffs(heavym) - 1; heavym &= heavym - 1;
#pragma unroll
                    for (int s = 0; s < 2; s++) {
                        int j = 64 * c + 32 * s + lane;
                        float sc = exact_score(f, emb, sH, j);
                        if (sc > lb || (sc == lb && j < lj)) { lb = sc; lj = j; }
                    }
                }
#pragma unroll
                for (int m = 16; m; m >>= 1) {
                    float ob = __shfl_xor_sync(0xffffffffu, lb, m);
                    int   oj = __shfl_xor_sync(0xffffffffu, lj, m);
                    if (ob > lb || (ob == lb && oj < lj)) { lb = ob; lj = oj; }
                }
                if (lane == 0) sBI[rowl] = lj;
            }
            __syncthreads();
            // ---- deferred epilogue for flagged rows ----
            if (mine_flagged) do_epilogue(sBI[myrow]);
        }
    }

    // ---- final merges ----
    __syncthreads();
#pragma unroll
    for (int i = 0; i < 2; i++) {
        float c = sCnt[tid + 256 * i];
        if (c != 0.0f) atomicAdd(&g_counts[tid + 256 * i], c);
    }
#pragma unroll
    for (int m = 16; m; m >>= 1) sse_acc += __shfl_xor_sync(0xffffffffu, sse_acc, m);
    if (lane == 0 && sse_acc != 0.0f) atomicAdd(&g_sse, sse_acc);
}

// ============================================================================
// Kernel 3: finalize EMA + loss. 64 blocks x 512 thr.
// ============================================================================
__global__ void vq_final(const float* __restrict__ cluster_size,
                         const float* __restrict__ embedding_avg,
                         float* __restrict__ out) {
    __shared__ float sncs[NC];
    __shared__ float sred[NC];
    const int t = threadIdx.x;
    const int b = blockIdx.x;

    float ncs = cluster_size[t] * 0.99f + 0.01f * g_counts[t];
    sncs[t] = ncs;
    sred[t] = ncs;
    if (b == 0) out[O_NCS + t] = ncs;
    __syncthreads();
#pragma unroll
    for (int o = NC / 2; o > 0; o >>= 1) {
        if (t < o) sred[t] += sred[t + o];
        __syncthreads();
    }
    const float n = sred[0];

    const int code = 8 * b + (t >> 6);
    const int k = t & 63;
    const size_t o = (size_t)code * CD + k;
    float ea = embedding_avg[o] * 0.99f + 0.01f * g_esum[o];
    out[O_NAVG + o] = ea;
    float cs = (sncs[code] + 1e-6f) / (n + (float)NC * 1e-6f);
    out[O_NEMB + o] = ea / cs;

    if (b == 0 && t == 0) out[O_LOSS] = 0.25f * g_sse / (float)NELEM;
}

// ============================================================================
extern "C" void kernel_launch(void* const* d_in, const int* in_sizes, int n_in,
                              void* d_out, int out_size) {
    const float* z    = (const float*)d_in[0];
    const float* emb  = (const float*)d_in[1];
    const float* csz  = (const float*)d_in[2];
    const float* eavg = (const float*)d_in[3];
    float* out = (float*)d_out;

    cudaFuncSetAttribute(vq_main, cudaFuncAttributeMaxDynamicSharedMemorySize, SMEM_SZ);
    vq_init<<<64, 512>>>(emb);
    vq_nop1<<<1, 1>>>();
    vq_nop2<<<1, 1>>>();
    vq_main<<<GRID, 256, SMEM_SZ>>>(z, emb, out);
    vq_final<<<64, NC>>>(csz, eavg, out);
}

// round 13
// speedup vs baseline: 1.1324x; 1.1324x over previous
#include <cuda_runtime.h>
#include <cuda_fp16.h>
#include <cstdint>

// ============================================================================
// VectorQuantizerEMA — persistent 3-CTA/SM HMMA (24 warps/SM), single-pass
// fp16 scoring, per-tile B reload (pair-chunk layout), packed-key argmax,
// candidate-pruned exact fp32 recheck.
// ============================================================================

#define NC      512
#define CD      64
#define NROWS   (64 * 4096)
#define NELEM   (NROWS * CD)
#define TROWS   64
#define NTILES  (NROWS / TROWS)     // 4096
#define GRID    444                 // 3 CTAs per SM
#define TAU     0.20f

#define O_ZQ    ((size_t)0)
#define O_LOSS  ((size_t)16777216)
#define O_IDX   ((size_t)16777217)
#define O_NEMB  ((size_t)17039361)
#define O_NCS   ((size_t)17072129)
#define O_NAVG  ((size_t)17072641)

// ---- device scratch --------------------------------------------------------
__device__ __align__(16) float g_esum[NC * CD];
// B fp16 in pair-chunk layout: ushort idx = (code*32 + l4*8 + c)*2 + (k&1)
// where u32chunk c (0..7) holds row_u32[l4 + 4c], l4 = lane&3 slice.
__device__ __align__(16) unsigned short g_Bp[NC * CD];
__device__ float g_counts[NC];
__device__ float g_h[NC];            // 0.5*||e||^2
__device__ float g_sse;

// ---- smem layout (bytes, per CTA) ------------------------------------------
#define SM_Z0    0        // 16KB raw z tile buf A
#define SM_Z1    16384    // 16KB raw z tile buf B
#define SM_AH    32768    // 8KB fp16 A, swizzled
#define SM_R2    40960    // 8KB uint2 (key1,key2) per (row, warp*2+h) 64x16
#define SM_H     49152    // 2KB
#define SM_CNT   51200    // 2KB
#define SM_BI    53248    // 256B
#define SM_BEST  53504    // 256B
#define SM_LIST  53760    // 256B
#define SM_FLG   54016    // 64B
#define SM_NFLG  54080
#define SMEM_SZ  54144

__device__ __forceinline__ uint32_t smem_u32(const void* p) {
    uint32_t a;
    asm("{ .reg .u64 t; cvta.to.shared.u64 t, %1; cvt.u32.u64 %0, t; }" : "=r"(a) : "l"(p));
    return a;
}
__device__ __forceinline__ void ldsm_x4(uint32_t a, uint32_t* r) {
    asm volatile("ldmatrix.sync.aligned.m8n8.x4.shared.b16 {%0,%1,%2,%3}, [%4];"
        : "=r"(r[0]), "=r"(r[1]), "=r"(r[2]), "=r"(r[3]) : "r"(a));
}
__device__ __forceinline__ void mma16816(float* c, const uint32_t* a,
                                         uint32_t b0, uint32_t b1) {
    asm volatile("mma.sync.aligned.m16n8k16.row.col.f32.f16.f16.f32 "
        "{%0,%1,%2,%3}, {%4,%5,%6,%7}, {%8,%9}, {%0,%1,%2,%3};"
        : "+f"(c[0]), "+f"(c[1]), "+f"(c[2]), "+f"(c[3])
        : "r"(a[0]), "r"(a[1]), "r"(a[2]), "r"(a[3]), "r"(b0), "r"(b1));
}
__device__ __forceinline__ uint32_t packh(float x, float y) {
    __half2 h = __floats2half2_rn(x, y);
    return *(uint32_t*)&h;
}
__device__ __forceinline__ void cp16(uint32_t d, const void* s) {
    asm volatile("cp.async.cg.shared.global [%0], [%1], 16;" :: "r"(d), "l"(s));
}
#define CP_COMMIT() asm volatile("cp.async.commit_group;")
#define CP_WAIT0()  asm volatile("cp.async.wait_group 0;")

// ---- packed monotonic keys -------------------------------------------------
__device__ __forceinline__ uint32_t mkkey(float s, int j) {
    uint32_t u = __float_as_uint(s);
    u ^= (uint32_t)((int32_t)u >> 31) | 0x80000000u;
    return (u & 0xFFFFFE00u) | (uint32_t)(511 - j);
}
__device__ __forceinline__ float dkey(uint32_t k) {
    uint32_t u = k & 0xFFFFFE00u;
    u = (u & 0x80000000u) ? (u ^ 0x80000000u) : ~u;
    return __uint_as_float(u);
}
__device__ __forceinline__ uint32_t umaxu(uint32_t a, uint32_t b) { return a > b ? a : b; }
__device__ __forceinline__ uint32_t uminu(uint32_t a, uint32_t b) { return a < b ? a : b; }
__device__ __forceinline__ void pmerge(uint32_t& m1, uint32_t& m2,
                                       uint32_t hi, uint32_t lo) {
    m2 = umaxu(umaxu(m2, lo), uminu(m1, hi));
    m1 = umaxu(m1, hi);
}

__device__ __forceinline__ float exact_score(const float4* __restrict__ f,
                                             const float* __restrict__ emb,
                                             const float* __restrict__ sH, int j) {
    const float4* er = (const float4*)(emb + (size_t)j * CD);
    float acc = 0.0f;
#pragma unroll
    for (int i = 0; i < 16; i++) {
        float4 e = er[i];
        acc += f[i].x * e.x + f[i].y * e.y + f[i].z * e.z + f[i].w * e.w;
    }
    return acc - sH[j];
}

// ============================================================================
// Kernel 1: zero scratch, half-norms, fp16 B in pair-chunk layout
// ============================================================================
__global__ void vq_init(const float* __restrict__ emb) {
    int t = blockIdx.x * blockDim.x + threadIdx.x;   // 32768
    if (t < NC * CD) {
        g_esum[t] = 0.0f;
        int j = t >> 6, k = t & 63;
        int u32i = k >> 1;                     // 0..31
        int l4 = u32i & 3, c = u32i >> 2;      // lane slice, chunk
        g_Bp[((j * 32) + l4 * 8 + c) * 2 + (k & 1)] =
            __half_as_ushort(__float2half_rn(emb[t]));
    }
    if (t == 0) g_sse = 0.0f;
    if (t < NC) {
        g_counts[t] = 0.0f;
        const float4* e = (const float4*)(emb + (size_t)t * CD);
        float s = 0.0f;
#pragma unroll
        for (int i = 0; i < CD / 4; i++) {
            float4 v = e[i];
            s += v.x * v.x + v.y * v.y + v.z * v.z + v.w * v.w;
        }
        g_h[t] = 0.5f * s;
    }
}

// no-op spacers so ncu -s 5 lands on vq_main
__global__ void vq_nop1() {}
__global__ void vq_nop2() {}

// ============================================================================
// Kernel 2: persistent main. 444 CTAs x 256 thr (8 warps), 64-row tiles,
// 3 CTAs/SM. Warp w owns codes [64w,64w+64) via two 32-code halves.
// ============================================================================
__global__ void __launch_bounds__(256, 3)
vq_main(const float* __restrict__ z, const float* __restrict__ emb,
        float* __restrict__ out) {
    extern __shared__ __align__(16) char smem[];
    const uint32_t sb32 = smem_u32(smem);
    float*  sH   = (float*)(smem + SM_H);
    float*  sCnt = (float*)(smem + SM_CNT);
    int*    sBI  = (int*)(smem + SM_BI);
    float*  sBest= (float*)(smem + SM_BEST);
    int*    sLst = (int*)(smem + SM_LIST);
    unsigned char* sFlg = (unsigned char*)(smem + SM_FLG);
    int*    sNF  = (int*)(smem + SM_NFLG);
    uint2*  sR2  = (uint2*)(smem + SM_R2);

    const int tid  = threadIdx.x;
    const int wid  = tid >> 5;      // 0..7
    const int lane = tid & 31;

    // ---- prologue: prefetch first tile; stage h; zero counters ----
    {
        uint32_t dst = sb32 + SM_Z0;
        const char* src = (const char*)(z + (size_t)blockIdx.x * TROWS * CD);
#pragma unroll
        for (int i = 0; i < 4; i++) {
            int c = tid + i * 256;
            cp16(dst + c * 16, src + c * 16);
        }
        CP_COMMIT();
    }
#pragma unroll
    for (int i = 0; i < 2; i++) {
        sH[tid + 256 * i] = g_h[tid + 256 * i];
        sCnt[tid + 256 * i] = 0.0f;
    }
    __syncthreads();

    const int jw = wid * 64;
    const int myrow = tid >> 2;          // 0..63
    const int myq   = tid & 3;

    float sse_acc = 0.0f;
    int it = 0;
#pragma unroll 1
    for (int tile = blockIdx.x; tile < NTILES; tile += GRID, it++) {
        const uint32_t zoff = (it & 1) ? SM_Z1 : SM_Z0;

        CP_WAIT0();
        __syncthreads();                 // cur z resident; prev phases done

        // ---- convert: z quarter -> fp16 AH (swizzled) ----
        {
            const float4* zr = (const float4*)(smem + zoff + myrow * 256 + myq * 64);
            float4 v0 = zr[0], v1 = zr[1], v2 = zr[2], v3 = zr[3];
            uint4 H0, H1;
            H0.x = packh(v0.x, v0.y); H0.y = packh(v0.z, v0.w);
            H0.z = packh(v1.x, v1.y); H0.w = packh(v1.z, v1.w);
            H1.x = packh(v2.x, v2.y); H1.y = packh(v2.z, v2.w);
            H1.z = packh(v3.x, v3.y); H1.w = packh(v3.z, v3.w);
            uint4* pH = (uint4*)(smem + SM_AH + myrow * 128);
            pH[(2 * myq) ^ (myrow & 7)]     = H0;
            pH[(2 * myq + 1) ^ (myrow & 7)] = H1;
        }
        if (tid == 0) *sNF = 0;
        __syncthreads();

        // ---- prefetch next tile into other buffer (overlaps MMA) ----
        {
            int tn = tile + GRID;
            if (tn < NTILES) {
                uint32_t dst = sb32 + ((it & 1) ? SM_Z0 : SM_Z1);
                const char* src = (const char*)(z + (size_t)tn * TROWS * CD);
#pragma unroll
                for (int i = 0; i < 4; i++) {
                    int c = tid + i * 256;
                    cp16(dst + c * 16, src + c * 16);
                }
            }
            CP_COMMIT();
        }

        // ---- MMA: h-outer (load B half once), rt-inner ----
#pragma unroll 1
        for (int h = 0; h < 2; h++) {
            // load this half's B fragments: 4 nt x (ks-pairs) = 32 regs
            uint32_t Breg[4][8];
#pragma unroll
            for (int nt = 0; nt < 4; nt++) {
                int code = jw + 32 * h + nt * 8 + (lane >> 2);
                const uint4* bp = (const uint4*)g_Bp + (size_t)code * 8 + (lane & 3) * 2;
                uint4 q0 = bp[0], q1 = bp[1];
                Breg[nt][0] = q0.x; Breg[nt][1] = q0.y;
                Breg[nt][2] = q0.z; Breg[nt][3] = q0.w;
                Breg[nt][4] = q1.x; Breg[nt][5] = q1.y;
                Breg[nt][6] = q1.z; Breg[nt][7] = q1.w;
            }
            // half-norms for this half's 8 per-lane slots (packed)
            __half2 hreg2[4];
#pragma unroll
            for (int n4 = 0; n4 < 4; n4++) {
                int j0 = jw + 32 * h + n4 * 8 + 2 * (lane & 3);
                hreg2[n4] = __floats2half2_rn(sH[j0], sH[j0 + 1]);
            }

#pragma unroll 1
            for (int rt = 0; rt < 4; rt++) {
                uint32_t Ah[16];
                {
                    int rl = 16 * rt + (lane & 7) + (((lane >> 3) & 1) << 3);
                    int ch = (lane >> 4) & 1;
                    uint32_t baseH = sb32 + SM_AH + rl * 128;
                    int sw = rl & 7;
#pragma unroll
                    for (int ks = 0; ks < 4; ks++)
                        ldsm_x4(baseH + (((2 * ks + ch) ^ sw) << 4), &Ah[ks * 4]);
                }
                uint32_t a1 = 0, a2 = 0, b1 = 0, b2 = 0;
#pragma unroll
                for (int p = 0; p < 2; p++) {        // 2-nt chunks, C stays 8
                    float C[8];
#pragma unroll
                    for (int i = 0; i < 8; i++) C[i] = 0.0f;
#pragma unroll
                    for (int q = 0; q < 2; q++) {
                        int nt = 2 * p + q;
#pragma unroll
                        for (int ks = 0; ks < 4; ks++)
                            mma16816(&C[q * 4], &Ah[ks * 4],
                                     Breg[nt][2 * ks], Breg[nt][2 * ks + 1]);
                    }
#pragma unroll
                    for (int q = 0; q < 2; q++) {
                        int n4 = 2 * p + q;
                        float2 hh = __half22float2(hreg2[n4]);
                        int j0 = jw + 32 * h + n4 * 8 + 2 * (lane & 3);
                        uint32_t k0 = mkkey(C[q * 4 + 0] - hh.x, j0);
                        uint32_t k1 = mkkey(C[q * 4 + 1] - hh.y, j0 + 1);
                        uint32_t hi = umaxu(k0, k1), lo = uminu(k0, k1);
                        if (p == 0 && q == 0) { a1 = hi; a2 = lo; }
                        else                  pmerge(a1, a2, hi, lo);
                        k0 = mkkey(C[q * 4 + 2] - hh.x, j0);
                        k1 = mkkey(C[q * 4 + 3] - hh.y, j0 + 1);
                        hi = umaxu(k0, k1); lo = uminu(k0, k1);
                        if (p == 0 && q == 0) { b1 = hi; b2 = lo; }
                        else                  pmerge(b1, b2, hi, lo);
                    }
                }
                // cross-lane top-2 over 4 lanes sharing each row
#pragma unroll
                for (int m = 1; m <= 2; m <<= 1) {
                    uint32_t o1 = __shfl_xor_sync(0xffffffffu, a1, m);
                    uint32_t o2 = __shfl_xor_sync(0xffffffffu, a2, m);
                    pmerge(a1, a2, umaxu(o1, o2), uminu(o1, o2));
                    o1 = __shfl_xor_sync(0xffffffffu, b1, m);
                    o2 = __shfl_xor_sync(0xffffffffu, b2, m);
                    pmerge(b1, b2, umaxu(o1, o2), uminu(o1, o2));
                }
                if ((lane & 3) == 0) {
                    int g = lane >> 2;
                    int slot = wid * 2 + h;          // block slot: codes [32*slot,+32)
                    sR2[(16 * rt + g) * 16 + slot]     = make_uint2(a1, a2);
                    sR2[(16 * rt + g + 8) * 16 + slot] = make_uint2(b1, b2);
                }
            }
        }
        __syncthreads();

        // ---- per-row combine: 2 threads/row, 8 slots each, then 1 shfl ----
        if (tid < 128) {
            int row = tid >> 1, half = tid & 1;
            uint2 v0 = sR2[row * 16 + half * 8];
            uint32_t m1 = v0.x, m2 = v0.y;
#pragma unroll
            for (int w = 1; w < 8; w++) {
                uint2 v = sR2[row * 16 + half * 8 + w];
                pmerge(m1, m2, v.x, v.y);
            }
            uint32_t o1 = __shfl_xor_sync(0xffffffffu, m1, 1);
            uint32_t o2 = __shfl_xor_sync(0xffffffffu, m2, 1);
            pmerge(m1, m2, o1, o2);
            if (half == 0) {
                float f1 = dkey(m1), f2 = dkey(m2);
                sBI[row] = 511 - (int)(m1 & 0x1FFu);
                sBest[row] = f1;
                int flag = (f1 - f2 < TAU) ? 1 : 0;
                sFlg[row] = (unsigned char)flag;
                if (flag) {
                    int p = atomicAdd(sNF, 1);
                    sLst[p] = row;
                }
            }
        }
        __syncthreads();
        const int nflag = *sNF;
        const bool mine_flagged = sFlg[myrow] != 0;

        // ---- epilogue helper (z from smem zoff) ----
        auto do_epilogue = [&](int bi) {
            size_t rg = (size_t)tile * TROWS + myrow;
            if (myq == 0) {
                out[O_IDX + rg] = (float)bi;
                atomicAdd(&sCnt[bi], 1.0f);
            }
            const float4* er = (const float4*)(emb + (size_t)bi * CD + myq * 16);
            const float4* zr = (const float4*)(smem + zoff + myrow * 256 + myq * 64);
            float4* oq = (float4*)(out + O_ZQ + rg * CD + myq * 16);
            float* es = g_esum + (size_t)bi * CD + myq * 16;
#pragma unroll
            for (int i = 0; i < 4; i++) {
                float4 e = er[i], zf = zr[i];
                float d0 = e.x - zf.x, d1 = e.y - zf.y;
                float d2 = e.z - zf.z, d3 = e.w - zf.w;
                sse_acc += d0 * d0 + d1 * d1 + d2 * d2 + d3 * d3;
                oq[i] = make_float4(zf.x + d0, zf.y + d1, zf.z + d2, zf.w + d3);
                asm volatile("red.global.add.v4.f32 [%0], {%1,%2,%3,%4};"
                    :: "l"(es + i * 4), "f"(zf.x), "f"(zf.y), "f"(zf.z), "f"(zf.w)
                    : "memory");
            }
        };

        // ---- epilogue for unflagged rows (overlaps recheck below) ----
        if (!mine_flagged) do_epilogue(sBI[myrow]);

        // ---- candidate-pruned exact recheck (one warp per flagged row) ----
        if (nflag > 0) {
#pragma unroll 1
            for (int li = wid; li < nflag; li += 8) {
                int rowl = sLst[li];
                float thr = sBest[rowl] - TAU;
                float wb = -3.4e38f, wb2 = -3.4e38f; int wic = 0;
                if (lane < 16) {
                    uint2 v = sR2[rowl * 16 + lane];
                    wb = dkey(v.x); wb2 = dkey(v.y);
                    wic = 511 - (int)(v.x & 0x1FFu);
                }
                unsigned candm  = __ballot_sync(0xffffffffu, wb  >= thr);
                unsigned heavym = __ballot_sync(0xffffffffu, wb  >= thr && wb2 >= thr);
                unsigned lightm = candm & ~heavym;

                float4 f[16];
                {
                    const float4* zr = (const float4*)(smem + zoff + rowl * 256);
#pragma unroll
                    for (int i = 0; i < 16; i++) f[i] = zr[i];
                }
                float lb = -3.4e38f; int lj = NC;
                if (lightm & (1u << lane)) {
                    lb = exact_score(f, emb, sH, wic);
                    lj = wic;
                }
#pragma unroll 1
                while (heavym) {       // heavy block = 32 codes -> 1 scan
                    int c = __ffs(heavym) - 1; heavym &= heavym - 1;
                    int j = 32 * c + lane;
                    float sc = exact_score(f, emb, sH, j);
                    if (sc > lb || (sc == lb && j < lj)) { lb = sc; lj = j; }
                }
#pragma unroll
                for (int m = 16; m; m >>= 1) {
                    float ob = __shfl_xor_sync(0xffffffffu, lb, m);
                    int   oj = __shfl_xor_sync(0xffffffffu, lj, m);
                    if (ob > lb || (ob == lb && oj < lj)) { lb = ob; lj = oj; }
                }
                if (lane == 0) sBI[rowl] = lj;
            }
            __syncthreads();
            // ---- deferred epilogue for flagged rows ----
            if (mine_flagged) do_epilogue(sBI[myrow]);
        }
    }

    // ---- final merges ----
    __syncthreads();
#pragma unroll
    for (int i = 0; i < 2; i++) {
        float c = sCnt[tid + 256 * i];
        if (c != 0.0f) atomicAdd(&g_counts[tid + 256 * i], c);
    }
#pragma unroll
    for (int m = 16; m; m >>= 1) sse_acc += __shfl_xor_sync(0xffffffffu, sse_acc, m);
    if (lane == 0 && sse_acc != 0.0f) atomicAdd(&g_sse, sse_acc);
}

// ============================================================================
// Kernel 3: finalize EMA + loss. 64 blocks x 512 thr.
// ============================================================================
__global__ void vq_final(const float* __restrict__ cluster_size,
                         const float* __restrict__ embedding_avg,
                         float* __restrict__ out) {
    __shared__ float sncs[NC];
    __shared__ float sred[NC];
    const int t = threadIdx.x;
    const int b = blockIdx.x;

    float ncs = cluster_size[t] * 0.99f + 0.01f * g_counts[t];
    sncs[t] = ncs;
    sred[t] = ncs;
    if (b == 0) out[O_NCS + t] = ncs;
    __syncthreads();
#pragma unroll
    for (int o = NC / 2; o > 0; o >>= 1) {
        if (t < o) sred[t] += sred[t + o];
        __syncthreads();
    }
    const float n = sred[0];

    const int code = 8 * b + (t >> 6);
    const int k = t & 63;
    const size_t o = (size_t)code * CD + k;
    float ea = embedding_avg[o] * 0.99f + 0.01f * g_esum[o];
    out[O_NAVG + o] = ea;
    float cs = (sncs[code] + 1e-6f) / (n + (float)NC * 1e-6f);
    out[O_NEMB + o] = ea / cs;

    if (b == 0 && t == 0) out[O_LOSS] = 0.25f * g_sse / (float)NELEM;
}

// ============================================================================
extern "C" void kernel_launch(void* const* d_in, const int* in_sizes, int n_in,
                              void* d_out, int out_size) {
    const float* z    = (const float*)d_in[0];
    const float* emb  = (const float*)d_in[1];
    const float* csz  = (const float*)d_in[2];
    const float* eavg = (const float*)d_in[3];
    float* out = (float*)d_out;

    cudaFuncSetAttribute(vq_main, cudaFuncAttributeMaxDynamicSharedMemorySize, SMEM_SZ);
    vq_init<<<64, 512>>>(emb);
    vq_nop1<<<1, 1>>>();
    vq_nop2<<<1, 1>>>();
    vq_main<<<GRID, 256, SMEM_SZ>>>(z, emb, out);
    vq_final<<<64, NC>>>(csz, eavg, out);
}

// round 16
// speedup vs baseline: 1.1550x; 1.0199x over previous
#include <cuda_runtime.h>
#include <cuda_fp16.h>
#include <cstdint>

// ============================================================================
// VectorQuantizerEMA — persistent 3-CTA/SM HMMA (24 warps/SM), R13 numerics
// (sign-folded keys, half2 norms, TAU=0.20) + dynamic tile scheduler.
// ============================================================================

#define NC      512
#define CD      64
#define NROWS   (64 * 4096)
#define NELEM   (NROWS * CD)
#define TROWS   64
#define NTILES  (NROWS / TROWS)     // 4096
#define GRID    444                 // 3 CTAs per SM
#define TAU     0.20f

#define O_ZQ    ((size_t)0)
#define O_LOSS  ((size_t)16777216)
#define O_IDX   ((size_t)16777217)
#define O_NEMB  ((size_t)17039361)
#define O_NCS   ((size_t)17072129)
#define O_NAVG  ((size_t)17072641)

// ---- device scratch --------------------------------------------------------
__device__ __align__(16) float g_esum[NC * CD];
// B fp16 pair-chunk layout: ushort idx = (code*32 + l4*8 + c)*2 + (k&1)
__device__ __align__(16) unsigned short g_Bp[NC * CD];
__device__ float g_counts[NC];
__device__ float g_h[NC];            // 0.5*||e||^2
__device__ float g_sse;
__device__ int   g_tile;             // dynamic tile counter

// ---- smem layout (bytes, per CTA) ------------------------------------------
#define SM_Z0    0        // 16KB raw z tile buf A
#define SM_Z1    16384    // 16KB raw z tile buf B
#define SM_AH    32768    // 8KB fp16 A, swizzled
#define SM_R2    40960    // 8KB uint2 keys per (row, warp*2+h) 64x16
#define SM_H     49152    // 2KB
#define SM_CNT   51200    // 2KB
#define SM_BI    53248    // 256B
#define SM_BEST  53504    // 256B
#define SM_LIST  53760    // 256B
#define SM_FLG   54016    // 64B
#define SM_NFLG  54080    // 4B
#define SM_NXT   54084    // 4B
#define SMEM_SZ  54144

__device__ __forceinline__ uint32_t smem_u32(const void* p) {
    uint32_t a;
    asm("{ .reg .u64 t; cvta.to.shared.u64 t, %1; cvt.u32.u64 %0, t; }" : "=r"(a) : "l"(p));
    return a;
}
__device__ __forceinline__ void ldsm_x4(uint32_t a, uint32_t* r) {
    asm volatile("ldmatrix.sync.aligned.m8n8.x4.shared.b16 {%0,%1,%2,%3}, [%4];"
        : "=r"(r[0]), "=r"(r[1]), "=r"(r[2]), "=r"(r[3]) : "r"(a));
}
__device__ __forceinline__ void mma16816(float* c, const uint32_t* a,
                                         uint32_t b0, uint32_t b1) {
    asm volatile("mma.sync.aligned.m16n8k16.row.col.f32.f16.f16.f32 "
        "{%0,%1,%2,%3}, {%4,%5,%6,%7}, {%8,%9}, {%0,%1,%2,%3};"
        : "+f"(c[0]), "+f"(c[1]), "+f"(c[2]), "+f"(c[3])
        : "r"(a[0]), "r"(a[1]), "r"(a[2]), "r"(a[3]), "r"(b0), "r"(b1));
}
__device__ __forceinline__ uint32_t packh(float x, float y) {
    __half2 h = __floats2half2_rn(x, y);
    return *(uint32_t*)&h;
}
__device__ __forceinline__ void cp16(uint32_t d, const void* s) {
    asm volatile("cp.async.cg.shared.global [%0], [%1], 16;" :: "r"(d), "l"(s));
}
#define CP_COMMIT() asm volatile("cp.async.commit_group;")
#define CP_WAIT0()  asm volatile("cp.async.wait_group 0;")

// ---- packed monotonic keys (R13: sign-folded, works for any sign) ----------
__device__ __forceinline__ uint32_t mkkey(float s, int j) {
    uint32_t u = __float_as_uint(s);
    u ^= (uint32_t)((int32_t)u >> 31) | 0x80000000u;
    return (u & 0xFFFFFE00u) | (uint32_t)(511 - j);
}
__device__ __forceinline__ float dkey(uint32_t k) {
    uint32_t u = k & 0xFFFFFE00u;
    u = (u & 0x80000000u) ? (u ^ 0x80000000u) : ~u;
    return __uint_as_float(u);
}
__device__ __forceinline__ uint32_t umaxu(uint32_t a, uint32_t b) { return a > b ? a : b; }
__device__ __forceinline__ uint32_t uminu(uint32_t a, uint32_t b) { return a < b ? a : b; }
__device__ __forceinline__ void pmerge(uint32_t& m1, uint32_t& m2,
                                       uint32_t hi, uint32_t lo) {
    m2 = umaxu(umaxu(m2, lo), uminu(m1, hi));
    m1 = umaxu(m1, hi);
}

__device__ __forceinline__ float exact_score(const float4* __restrict__ f,
                                             const float* __restrict__ emb,
                                             const float* __restrict__ sH, int j) {
    const float4* er = (const float4*)(emb + (size_t)j * CD);
    float acc = 0.0f;
#pragma unroll
    for (int i = 0; i < 16; i++) {
        float4 e = er[i];
        acc += f[i].x * e.x + f[i].y * e.y + f[i].z * e.z + f[i].w * e.w;
    }
    return acc - sH[j];
}

// ============================================================================
// Kernel 1: zero scratch, half-norms, fp16 B pair-chunk layout, tile counter
// ============================================================================
__global__ void vq_init(const float* __restrict__ emb) {
    int t = blockIdx.x * blockDim.x + threadIdx.x;   // 32768
    if (t < NC * CD) {
        g_esum[t] = 0.0f;
        int j = t >> 6, k = t & 63;
        int u32i = k >> 1;
        int l4 = u32i & 3, c = u32i >> 2;
        g_Bp[((j * 32) + l4 * 8 + c) * 2 + (k & 1)] =
            __half_as_ushort(__float2half_rn(emb[t]));
    }
    if (t == 0) { g_sse = 0.0f; g_tile = GRID; }
    if (t < NC) {
        g_counts[t] = 0.0f;
        const float4* e = (const float4*)(emb + (size_t)t * CD);
        float s = 0.0f;
#pragma unroll
        for (int i = 0; i < CD / 4; i++) {
            float4 v = e[i];
            s += v.x * v.x + v.y * v.y + v.z * v.z + v.w * v.w;
        }
        g_h[t] = 0.5f * s;
    }
}

// no-op spacers so ncu -s 5 lands on vq_main
__global__ void vq_nop1() {}
__global__ void vq_nop2() {}

// ============================================================================
// Kernel 2: persistent main. 444 CTAs x 256 thr (8 warps), 64-row tiles,
// 3 CTAs/SM, dynamic tile scheduling. Warp w: codes [64w,64w+64), 2 halves.
// ============================================================================
__global__ void __launch_bounds__(256, 3)
vq_main(const float* __restrict__ z, const float* __restrict__ emb,
        float* __restrict__ out) {
    extern __shared__ __align__(16) char smem[];
    const uint32_t sb32 = smem_u32(smem);
    float*  sH   = (float*)(smem + SM_H);
    float*  sCnt = (float*)(smem + SM_CNT);
    int*    sBI  = (int*)(smem + SM_BI);
    float*  sBest= (float*)(smem + SM_BEST);
    int*    sLst = (int*)(smem + SM_LIST);
    unsigned char* sFlg = (unsigned char*)(smem + SM_FLG);
    int*    sNF  = (int*)(smem + SM_NFLG);
    int*    sNxt = (int*)(smem + SM_NXT);
    uint2*  sR2  = (uint2*)(smem + SM_R2);

    const int tid  = threadIdx.x;
    const int wid  = tid >> 5;
    const int lane = tid & 31;

    // ---- prologue: prefetch first (static) tile; stage h; zero counters ----
    {
        uint32_t dst = sb32 + SM_Z0;
        const char* src = (const char*)(z + (size_t)blockIdx.x * TROWS * CD);
#pragma unroll
        for (int i = 0; i < 4; i++) {
            int c = tid + i * 256;
            cp16(dst + c * 16, src + c * 16);
        }
        CP_COMMIT();
    }
#pragma unroll
    for (int i = 0; i < 2; i++) {
        sH[tid + 256 * i] = g_h[tid + 256 * i];
        sCnt[tid + 256 * i] = 0.0f;
    }
    __syncthreads();

    const int jw = wid * 64;
    const int myrow = tid >> 2;
    const int myq   = tid & 3;

    float sse_acc = 0.0f;
    int cur = blockIdx.x;
    int it = 0;
#pragma unroll 1
    while (cur < NTILES) {
        const uint32_t zoff = (it & 1) ? SM_Z1 : SM_Z0;
        const int tile = cur;

        if (tid == 0) *sNxt = atomicAdd(&g_tile, 1);
        CP_WAIT0();
        __syncthreads();                 // z[cur] resident; sNxt visible
        const int nxt = *sNxt;

        // ---- convert: z quarter -> fp16 AH (swizzled) ----
        {
            const float4* zr = (const float4*)(smem + zoff + myrow * 256 + myq * 64);
            float4 v0 = zr[0], v1 = zr[1], v2 = zr[2], v3 = zr[3];
            uint4 H0, H1;
            H0.x = packh(v0.x, v0.y); H0.y = packh(v0.z, v0.w);
            H0.z = packh(v1.x, v1.y); H0.w = packh(v1.z, v1.w);
            H1.x = packh(v2.x, v2.y); H1.y = packh(v2.z, v2.w);
            H1.z = packh(v3.x, v3.y); H1.w = packh(v3.z, v3.w);
            uint4* pH = (uint4*)(smem + SM_AH + myrow * 128);
            pH[(2 * myq) ^ (myrow & 7)]     = H0;
            pH[(2 * myq + 1) ^ (myrow & 7)] = H1;
        }
        if (tid == 0) *sNF = 0;
        __syncthreads();

        // ---- prefetch next (dynamic) tile into other buffer ----
        if (nxt < NTILES) {
            uint32_t dst = sb32 + ((it & 1) ? SM_Z0 : SM_Z1);
            const char* src = (const char*)(z + (size_t)nxt * TROWS * CD);
#pragma unroll
            for (int i = 0; i < 4; i++) {
                int c = tid + i * 256;
                cp16(dst + c * 16, src + c * 16);
            }
        }
        CP_COMMIT();

        // ---- MMA: h-outer (load B half once), rt-inner  (R13 numerics) ----
#pragma unroll 1
        for (int h = 0; h < 2; h++) {
            uint32_t Breg[4][8];
#pragma unroll
            for (int nt = 0; nt < 4; nt++) {
                int code = jw + 32 * h + nt * 8 + (lane >> 2);
                const uint4* bp = (const uint4*)g_Bp + (size_t)code * 8 + (lane & 3) * 2;
                uint4 q0 = bp[0], q1 = bp[1];
                Breg[nt][0] = q0.x; Breg[nt][1] = q0.y;
                Breg[nt][2] = q0.z; Breg[nt][3] = q0.w;
                Breg[nt][4] = q1.x; Breg[nt][5] = q1.y;
                Breg[nt][6] = q1.z; Breg[nt][7] = q1.w;
            }
            __half2 hreg2[4];
#pragma unroll
            for (int n4 = 0; n4 < 4; n4++) {
                int j0 = jw + 32 * h + n4 * 8 + 2 * (lane & 3);
                hreg2[n4] = __floats2half2_rn(sH[j0], sH[j0 + 1]);
            }

#pragma unroll 1
            for (int rt = 0; rt < 4; rt++) {
                uint32_t Ah[16];
                {
                    int rl = 16 * rt + (lane & 7) + (((lane >> 3) & 1) << 3);
                    int ch = (lane >> 4) & 1;
                    uint32_t baseH = sb32 + SM_AH + rl * 128;
                    int sw = rl & 7;
#pragma unroll
                    for (int ks = 0; ks < 4; ks++)
                        ldsm_x4(baseH + (((2 * ks + ch) ^ sw) << 4), &Ah[ks * 4]);
                }
                uint32_t a1 = 0, a2 = 0, b1 = 0, b2 = 0;
#pragma unroll
                for (int p = 0; p < 2; p++) {
                    float C[8];
#pragma unroll
                    for (int i = 0; i < 8; i++) C[i] = 0.0f;
#pragma unroll
                    for (int q = 0; q < 2; q++) {
                        int nt = 2 * p + q;
#pragma unroll
                        for (int ks = 0; ks < 4; ks++)
                            mma16816(&C[q * 4], &Ah[ks * 4],
                                     Breg[nt][2 * ks], Breg[nt][2 * ks + 1]);
                    }
#pragma unroll
                    for (int q = 0; q < 2; q++) {
                        int n4 = 2 * p + q;
                        float2 hh = __half22float2(hreg2[n4]);
                        int j0 = jw + 32 * h + n4 * 8 + 2 * (lane & 3);
                        uint32_t k0 = mkkey(C[q * 4 + 0] - hh.x, j0);
                        uint32_t k1 = mkkey(C[q * 4 + 1] - hh.y, j0 + 1);
                        uint32_t hi = umaxu(k0, k1), lo = uminu(k0, k1);
                        if (p == 0 && q == 0) { a1 = hi; a2 = lo; }
                        else                  pmerge(a1, a2, hi, lo);
                        k0 = mkkey(C[q * 4 + 2] - hh.x, j0);
                        k1 = mkkey(C[q * 4 + 3] - hh.y, j0 + 1);
                        hi = umaxu(k0, k1); lo = uminu(k0, k1);
                        if (p == 0 && q == 0) { b1 = hi; b2 = lo; }
                        else                  pmerge(b1, b2, hi, lo);
                    }
                }
#pragma unroll
                for (int m = 1; m <= 2; m <<= 1) {
                    uint32_t o1 = __shfl_xor_sync(0xffffffffu, a1, m);
                    uint32_t o2 = __shfl_xor_sync(0xffffffffu, a2, m);
                    pmerge(a1, a2, umaxu(o1, o2), uminu(o1, o2));
                    o1 = __shfl_xor_sync(0xffffffffu, b1, m);
                    o2 = __shfl_xor_sync(0xffffffffu, b2, m);
                    pmerge(b1, b2, umaxu(o1, o2), uminu(o1, o2));
                }
                if ((lane & 3) == 0) {
                    int g = lane >> 2;
                    int slot = wid * 2 + h;
                    sR2[(16 * rt + g) * 16 + slot]     = make_uint2(a1, a2);
                    sR2[(16 * rt + g + 8) * 16 + slot] = make_uint2(b1, b2);
                }
            }
        }
        __syncthreads();

        // ---- per-row combine: 2 threads/row, 8 slots each, then 1 shfl ----
        if (tid < 128) {
            int row = tid >> 1, half = tid & 1;
            uint2 v0 = sR2[row * 16 + half * 8];
            uint32_t m1 = v0.x, m2 = v0.y;
#pragma unroll
            for (int w = 1; w < 8; w++) {
                uint2 v = sR2[row * 16 + half * 8 + w];
                pmerge(m1, m2, v.x, v.y);
            }
            uint32_t o1 = __shfl_xor_sync(0xffffffffu, m1, 1);
            uint32_t o2 = __shfl_xor_sync(0xffffffffu, m2, 1);
            pmerge(m1, m2, o1, o2);
            if (half == 0) {
                float f1 = dkey(m1), f2 = dkey(m2);
                sBI[row] = 511 - (int)(m1 & 0x1FFu);
                sBest[row] = f1;
                int flag = (f1 - f2 < TAU) ? 1 : 0;
                sFlg[row] = (unsigned char)flag;
                if (flag) {
                    int p = atomicAdd(sNF, 1);
                    sLst[p] = row;
                }
            }
        }
        __syncthreads();
        const int nflag = *sNF;
        const bool mine_flagged = sFlg[myrow] != 0;

        // ---- epilogue helper (z from smem zoff) ----
        auto do_epilogue = [&](int bi) {
            size_t rg = (size_t)tile * TROWS + myrow;
            if (myq == 0) {
                out[O_IDX + rg] = (float)bi;
                atomicAdd(&sCnt[bi], 1.0f);
            }
            const float4* er = (const float4*)(emb + (size_t)bi * CD + myq * 16);
            const float4* zr = (const float4*)(smem + zoff + myrow * 256 + myq * 64);
            float4* oq = (float4*)(out + O_ZQ + rg * CD + myq * 16);
            float* es = g_esum + (size_t)bi * CD + myq * 16;
#pragma unroll
            for (int i = 0; i < 4; i++) {
                float4 e = er[i], zf = zr[i];
                float d0 = e.x - zf.x, d1 = e.y - zf.y;
                float d2 = e.z - zf.z, d3 = e.w - zf.w;
                sse_acc += d0 * d0 + d1 * d1 + d2 * d2 + d3 * d3;
                oq[i] = make_float4(zf.x + d0, zf.y + d1, zf.z + d2, zf.w + d3);
                asm volatile("red.global.add.v4.f32 [%0], {%1,%2,%3,%4};"
                    :: "l"(es + i * 4), "f"(zf.x), "f"(zf.y), "f"(zf.z), "f"(zf.w)
                    : "memory");
            }
        };

        // ---- epilogue for unflagged rows (overlaps recheck below) ----
        if (!mine_flagged) do_epilogue(sBI[myrow]);

        // ---- candidate-pruned exact recheck (one warp per flagged row) ----
        if (nflag > 0) {
#pragma unroll 1
            for (int li = wid; li < nflag; li += 8) {
                int rowl = sLst[li];
                float thr = sBest[rowl] - TAU;
                float wb = -3.4e38f, wb2 = -3.4e38f; int wic = 0;
                if (lane < 16) {
                    uint2 v = sR2[rowl * 16 + lane];
                    wb = dkey(v.x); wb2 = dkey(v.y);
                    wic = 511 - (int)(v.x & 0x1FFu);
                }
                unsigned candm  = __ballot_sync(0xffffffffu, wb  >= thr);
                unsigned heavym = __ballot_sync(0xffffffffu, wb  >= thr && wb2 >= thr);
                unsigned lightm = candm & ~heavym;

                float4 f[16];
                {
                    const float4* zr = (const float4*)(smem + zoff + rowl * 256);
#pragma unroll
                    for (int i = 0; i < 16; i++) f[i] = zr[i];
                }
                float lb = -3.4e38f; int lj = NC;
                if (lightm & (1u << lane)) {
                    lb = exact_score(f, emb, sH, wic);
                    lj = wic;
                }
#pragma unroll 1
                while (heavym) {       // heavy block = 32 codes -> 1 scan
                    int c = __ffs(heavym) - 1; heavym &= heavym - 1;
                    int j = 32 * c + lane;
                    float sc = exact_score(f, emb, sH, j);
                    if (sc > lb || (sc == lb && j < lj)) { lb = sc; lj = j; }
                }
#pragma unroll
                for (int m = 16; m; m >>= 1) {
                    float ob = __shfl_xor_sync(0xffffffffu, lb, m);
                    int   oj = __shfl_xor_sync(0xffffffffu, lj, m);
                    if (ob > lb || (ob == lb && oj < lj)) { lb = ob; lj = oj; }
                }
                if (lane == 0) sBI[rowl] = lj;
            }
            __syncthreads();
            // ---- deferred epilogue for flagged rows ----
            if (mine_flagged) do_epilogue(sBI[myrow]);
        }

        cur = nxt;
        it++;
    }

    // ---- final merges ----
    __syncthreads();
#pragma unroll
    for (int i = 0; i < 2; i++) {
        float c = sCnt[tid + 256 * i];
        if (c != 0.0f) atomicAdd(&g_counts[tid + 256 * i], c);
    }
#pragma unroll
    for (int m = 16; m; m >>= 1) sse_acc += __shfl_xor_sync(0xffffffffu, sse_acc, m);
    if (lane == 0 && sse_acc != 0.0f) atomicAdd(&g_sse, sse_acc);
}

// ============================================================================
// Kernel 3: finalize EMA + loss. 64 blocks x 512 thr.
// ============================================================================
__global__ void vq_final(const float* __restrict__ cluster_size,
                         const float* __restrict__ embedding_avg,
                         float* __restrict__ out) {
    __shared__ float sncs[NC];
    __shared__ float sred[NC];
    const int t = threadIdx.x;
    const int b = blockIdx.x;

    float ncs = cluster_size[t] * 0.99f + 0.01f * g_counts[t];
    sncs[t] = ncs;
    sred[t] = ncs;
    if (b == 0) out[O_NCS + t] = ncs;
    __syncthreads();
#pragma unroll
    for (int o = NC / 2; o > 0; o >>= 1) {
        if (t < o) sred[t] += sred[t + o];
        __syncthreads();
    }
    const float n = sred[0];

    const int code = 8 * b + (t >> 6);
    const int k = t & 63;
    const size_t o = (size_t)code * CD + k;
    float ea = embedding_avg[o] * 0.99f + 0.01f * g_esum[o];
    out[O_NAVG + o] = ea;
    float cs = (sncs[code] + 1e-6f) / (n + (float)NC * 1e-6f);
    out[O_NEMB + o] = ea / cs;

    if (b == 0 && t == 0) out[O_LOSS] = 0.25f * g_sse / (float)NELEM;
}

// ============================================================================
extern "C" void kernel_launch(void* const* d_in, const int* in_sizes, int n_in,
                              void* d_out, int out_size) {
    const float* z    = (const float*)d_in[0];
    const float* emb  = (const float*)d_in[1];
    const float* csz  = (const float*)d_in[2];
    const float* eavg = (const float*)d_in[3];
    float* out = (float*)d_out;

    cudaFuncSetAttribute(vq_main, cudaFuncAttributeMaxDynamicSharedMemorySize, SMEM_SZ);
    vq_init<<<64, 512>>>(emb);
    vq_nop1<<<1, 1>>>();
    vq_nop2<<<1, 1>>>();
    vq_main<<<GRID, 256, SMEM_SZ>>>(z, emb, out);
    vq_final<<<64, NC>>>(csz, eavg, out);
}

// round 17
// speedup vs baseline: 1.1589x; 1.0033x over previous
#include <cuda_runtime.h>
#include <cuda_fp16.h>
#include <cstdint>

// ============================================================================
// VectorQuantizerEMA — persistent 3-CTA/SM HMMA (24 warps/SM), R13 numerics
// (sign-folded keys, half2 norms, TAU=0.24) + dynamic tile scheduler.
// ============================================================================

#define NC      512
#define CD      64
#define NROWS   (64 * 4096)
#define NELEM   (NROWS * CD)
#define TROWS   64
#define NTILES  (NROWS / TROWS)     // 4096
#define GRID    444                 // 3 CTAs per SM
#define TAU     0.24f

#define O_ZQ    ((size_t)0)
#define O_LOSS  ((size_t)16777216)
#define O_IDX   ((size_t)16777217)
#define O_NEMB  ((size_t)17039361)
#define O_NCS   ((size_t)17072129)
#define O_NAVG  ((size_t)17072641)

// ---- device scratch --------------------------------------------------------
__device__ __align__(16) float g_esum[NC * CD];
// B fp16 pair-chunk layout: ushort idx = (code*32 + l4*8 + c)*2 + (k&1)
__device__ __align__(16) unsigned short g_Bp[NC * CD];
__device__ float g_counts[NC];
__device__ float g_h[NC];            // 0.5*||e||^2
__device__ float g_sse;
__device__ int   g_tile;             // dynamic tile counter

// ---- smem layout (bytes, per CTA) ------------------------------------------
#define SM_Z0    0        // 16KB raw z tile buf A
#define SM_Z1    16384    // 16KB raw z tile buf B
#define SM_AH    32768    // 8KB fp16 A, swizzled
#define SM_R2    40960    // 8KB uint2 keys per (row, warp*2+h) 64x16
#define SM_H     49152    // 2KB
#define SM_CNT   51200    // 2KB
#define SM_BI    53248    // 256B
#define SM_BEST  53504    // 256B
#define SM_LIST  53760    // 256B
#define SM_FLG   54016    // 64B
#define SM_NFLG  54080    // 4B
#define SM_NXT   54084    // 4B
#define SMEM_SZ  54144

__device__ __forceinline__ uint32_t smem_u32(const void* p) {
    uint32_t a;
    asm("{ .reg .u64 t; cvta.to.shared.u64 t, %1; cvt.u32.u64 %0, t; }" : "=r"(a) : "l"(p));
    return a;
}
__device__ __forceinline__ void ldsm_x4(uint32_t a, uint32_t* r) {
    asm volatile("ldmatrix.sync.aligned.m8n8.x4.shared.b16 {%0,%1,%2,%3}, [%4];"
        : "=r"(r[0]), "=r"(r[1]), "=r"(r[2]), "=r"(r[3]) : "r"(a));
}
__device__ __forceinline__ void mma16816(float* c, const uint32_t* a,
                                         uint32_t b0, uint32_t b1) {
    asm volatile("mma.sync.aligned.m16n8k16.row.col.f32.f16.f16.f32 "
        "{%0,%1,%2,%3}, {%4,%5,%6,%7}, {%8,%9}, {%0,%1,%2,%3};"
        : "+f"(c[0]), "+f"(c[1]), "+f"(c[2]), "+f"(c[3])
        : "r"(a[0]), "r"(a[1]), "r"(a[2]), "r"(a[3]), "r"(b0), "r"(b1));
}
__device__ __forceinline__ uint32_t packh(float x, float y) {
    __half2 h = __floats2half2_rn(x, y);
    return *(uint32_t*)&h;
}
__device__ __forceinline__ void cp16(uint32_t d, const void* s) {
    asm volatile("cp.async.cg.shared.global [%0], [%1], 16;" :: "r"(d), "l"(s));
}
#define CP_COMMIT() asm volatile("cp.async.commit_group;")
#define CP_WAIT0()  asm volatile("cp.async.wait_group 0;")

// ---- packed monotonic keys (sign-folded; any sign) -------------------------
__device__ __forceinline__ uint32_t mkkey(float s, int j) {
    uint32_t u = __float_as_uint(s);
    u ^= (uint32_t)((int32_t)u >> 31) | 0x80000000u;
    return (u & 0xFFFFFE00u) | (uint32_t)(511 - j);
}
__device__ __forceinline__ float dkey(uint32_t k) {
    uint32_t u = k & 0xFFFFFE00u;
    u = (u & 0x80000000u) ? (u ^ 0x80000000u) : ~u;
    return __uint_as_float(u);
}
__device__ __forceinline__ uint32_t umaxu(uint32_t a, uint32_t b) { return a > b ? a : b; }
__device__ __forceinline__ uint32_t uminu(uint32_t a, uint32_t b) { return a < b ? a : b; }
__device__ __forceinline__ void pmerge(uint32_t& m1, uint32_t& m2,
                                       uint32_t hi, uint32_t lo) {
    m2 = umaxu(umaxu(m2, lo), uminu(m1, hi));
    m1 = umaxu(m1, hi);
}

__device__ __forceinline__ float exact_score(const float4* __restrict__ f,
                                             const float* __restrict__ emb,
                                             const float* __restrict__ sH, int j) {
    const float4* er = (const float4*)(emb + (size_t)j * CD);
    float acc = 0.0f;
#pragma unroll
    for (int i = 0; i < 16; i++) {
        float4 e = er[i];
        acc += f[i].x * e.x + f[i].y * e.y + f[i].z * e.z + f[i].w * e.w;
    }
    return acc - sH[j];
}

// ============================================================================
// Kernel 1: zero scratch, half-norms, fp16 B pair-chunk layout, tile counter
// ============================================================================
__global__ void vq_init(const float* __restrict__ emb) {
    int t = blockIdx.x * blockDim.x + threadIdx.x;   // 256*128 = 32768
    if (t < NC * CD) {
        g_esum[t] = 0.0f;
        int j = t >> 6, k = t & 63;
        int u32i = k >> 1;
        int l4 = u32i & 3, c = u32i >> 2;
        g_Bp[((j * 32) + l4 * 8 + c) * 2 + (k & 1)] =
            __half_as_ushort(__float2half_rn(emb[t]));
    }
    if (t == 0) { g_sse = 0.0f; g_tile = GRID; }
    if (t < NC) {
        g_counts[t] = 0.0f;
        const float4* e = (const float4*)(emb + (size_t)t * CD);
        float s = 0.0f;
#pragma unroll
        for (int i = 0; i < CD / 4; i++) {
            float4 v = e[i];
            s += v.x * v.x + v.y * v.y + v.z * v.z + v.w * v.w;
        }
        g_h[t] = 0.5f * s;
    }
}

// no-op spacers so ncu -s 5 lands on vq_main
__global__ void vq_nop1() {}
__global__ void vq_nop2() {}

// ============================================================================
// Kernel 2: persistent main. 444 CTAs x 256 thr (8 warps), 64-row tiles,
// 3 CTAs/SM, dynamic tile scheduling. Warp w: codes [64w,64w+64), 2 halves.
// ============================================================================
__global__ void __launch_bounds__(256, 3)
vq_main(const float* __restrict__ z, const float* __restrict__ emb,
        float* __restrict__ out) {
    extern __shared__ __align__(16) char smem[];
    const uint32_t sb32 = smem_u32(smem);
    float*  sH   = (float*)(smem + SM_H);
    float*  sCnt = (float*)(smem + SM_CNT);
    int*    sBI  = (int*)(smem + SM_BI);
    float*  sBest= (float*)(smem + SM_BEST);
    int*    sLst = (int*)(smem + SM_LIST);
    unsigned char* sFlg = (unsigned char*)(smem + SM_FLG);
    int*    sNF  = (int*)(smem + SM_NFLG);
    int*    sNxt = (int*)(smem + SM_NXT);
    uint2*  sR2  = (uint2*)(smem + SM_R2);

    const int tid  = threadIdx.x;
    const int wid  = tid >> 5;
    const int lane = tid & 31;

    // ---- prologue: prefetch first (static) tile; stage h; zero counters ----
    {
        uint32_t dst = sb32 + SM_Z0;
        const char* src = (const char*)(z + (size_t)blockIdx.x * TROWS * CD);
#pragma unroll
        for (int i = 0; i < 4; i++) {
            int c = tid + i * 256;
            cp16(dst + c * 16, src + c * 16);
        }
        CP_COMMIT();
    }
#pragma unroll
    for (int i = 0; i < 2; i++) {
        sH[tid + 256 * i] = g_h[tid + 256 * i];
        sCnt[tid + 256 * i] = 0.0f;
    }
    __syncthreads();

    const int jw = wid * 64;
    const int myrow = tid >> 2;
    const int myq   = tid & 3;

    float sse_acc = 0.0f;
    int cur = blockIdx.x;
    int it = 0;
#pragma unroll 1
    while (cur < NTILES) {
        const uint32_t zoff = (it & 1) ? SM_Z1 : SM_Z0;
        const int tile = cur;

        if (tid == 0) *sNxt = atomicAdd(&g_tile, 1);
        CP_WAIT0();
        __syncthreads();                 // z[cur] resident; sNxt visible
        const int nxt = *sNxt;

        // ---- convert: z quarter -> fp16 AH (swizzled) ----
        {
            const float4* zr = (const float4*)(smem + zoff + myrow * 256 + myq * 64);
            float4 v0 = zr[0], v1 = zr[1], v2 = zr[2], v3 = zr[3];
            uint4 H0, H1;
            H0.x = packh(v0.x, v0.y); H0.y = packh(v0.z, v0.w);
            H0.z = packh(v1.x, v1.y); H0.w = packh(v1.z, v1.w);
            H1.x = packh(v2.x, v2.y); H1.y = packh(v2.z, v2.w);
            H1.z = packh(v3.x, v3.y); H1.w = packh(v3.z, v3.w);
            uint4* pH = (uint4*)(smem + SM_AH + myrow * 128);
            pH[(2 * myq) ^ (myrow & 7)]     = H0;
            pH[(2 * myq + 1) ^ (myrow & 7)] = H1;
        }
        if (tid == 0) *sNF = 0;
        __syncthreads();

        // ---- prefetch next (dynamic) tile into other buffer ----
        if (nxt < NTILES) {
            uint32_t dst = sb32 + ((it & 1) ? SM_Z0 : SM_Z1);
            const char* src = (const char*)(z + (size_t)nxt * TROWS * CD);
#pragma unroll
            for (int i = 0; i < 4; i++) {
                int c = tid + i * 256;
                cp16(dst + c * 16, src + c * 16);
            }
        }
        CP_COMMIT();

        // ---- MMA: h-outer (load B half once), rt-inner ----
#pragma unroll 1
        for (int h = 0; h < 2; h++) {
            uint32_t Breg[4][8];
#pragma unroll
            for (int nt = 0; nt < 4; nt++) {
                int code = jw + 32 * h + nt * 8 + (lane >> 2);
                const uint4* bp = (const uint4*)g_Bp + (size_t)code * 8 + (lane & 3) * 2;
                uint4 q0 = bp[0], q1 = bp[1];
                Breg[nt][0] = q0.x; Breg[nt][1] = q0.y;
                Breg[nt][2] = q0.z; Breg[nt][3] = q0.w;
                Breg[nt][4] = q1.x; Breg[nt][5] = q1.y;
                Breg[nt][6] = q1.z; Breg[nt][7] = q1.w;
            }
            __half2 hreg2[4];
#pragma unroll
            for (int n4 = 0; n4 < 4; n4++) {
                int j0 = jw + 32 * h + n4 * 8 + 2 * (lane & 3);
                hreg2[n4] = __floats2half2_rn(sH[j0], sH[j0 + 1]);
            }

#pragma unroll 1
            for (int rt = 0; rt < 4; rt++) {
                uint32_t Ah[16];
                {
                    int rl = 16 * rt + (lane & 7) + (((lane >> 3) & 1) << 3);
                    int ch = (lane >> 4) & 1;
                    uint32_t baseH = sb32 + SM_AH + rl * 128;
                    int sw = rl & 7;
#pragma unroll
                    for (int ks = 0; ks < 4; ks++)
                        ldsm_x4(baseH + (((2 * ks + ch) ^ sw) << 4), &Ah[ks * 4]);
                }
                uint32_t a1 = 0, a2 = 0, b1 = 0, b2 = 0;
#pragma unroll
                for (int p = 0; p < 2; p++) {
                    float C[8];
#pragma unroll
                    for (int i = 0; i < 8; i++) C[i] = 0.0f;
#pragma unroll
                    for (int q = 0; q < 2; q++) {
                        int nt = 2 * p + q;
#pragma unroll
                        for (int ks = 0; ks < 4; ks++)
                            mma16816(&C[q * 4], &Ah[ks * 4],
                                     Breg[nt][2 * ks], Breg[nt][2 * ks + 1]);
                    }
#pragma unroll
                    for (int q = 0; q < 2; q++) {
                        int n4 = 2 * p + q;
                        float2 hh = __half22float2(hreg2[n4]);
                        int j0 = jw + 32 * h + n4 * 8 + 2 * (lane & 3);
                        uint32_t k0 = mkkey(C[q * 4 + 0] - hh.x, j0);
                        uint32_t k1 = mkkey(C[q * 4 + 1] - hh.y, j0 + 1);
                        uint32_t hi = umaxu(k0, k1), lo = uminu(k0, k1);
                        if (p == 0 && q == 0) { a1 = hi; a2 = lo; }
                        else                  pmerge(a1, a2, hi, lo);
                        k0 = mkkey(C[q * 4 + 2] - hh.x, j0);
                        k1 = mkkey(C[q * 4 + 3] - hh.y, j0 + 1);
                        hi = umaxu(k0, k1); lo = uminu(k0, k1);
                        if (p == 0 && q == 0) { b1 = hi; b2 = lo; }
                        else                  pmerge(b1, b2, hi, lo);
                    }
                }
#pragma unroll
                for (int m = 1; m <= 2; m <<= 1) {
                    uint32_t o1 = __shfl_xor_sync(0xffffffffu, a1, m);
                    uint32_t o2 = __shfl_xor_sync(0xffffffffu, a2, m);
                    pmerge(a1, a2, umaxu(o1, o2), uminu(o1, o2));
                    o1 = __shfl_xor_sync(0xffffffffu, b1, m);
                    o2 = __shfl_xor_sync(0xffffffffu, b2, m);
                    pmerge(b1, b2, umaxu(o1, o2), uminu(o1, o2));
                }
                if ((lane & 3) == 0) {
                    int g = lane >> 2;
                    int slot = wid * 2 + h;
                    sR2[(16 * rt + g) * 16 + slot]     = make_uint2(a1, a2);
                    sR2[(16 * rt + g + 8) * 16 + slot] = make_uint2(b1, b2);
                }
            }
        }
        __syncthreads();

        // ---- per-row combine: 2 threads/row, vectorized uint4 loads ----
        if (tid < 128) {
            int row = tid >> 1, half = tid & 1;
            const uint4* rp = (const uint4*)(sR2 + row * 16 + half * 8);
            uint4 w0 = rp[0], w1 = rp[1], w2 = rp[2], w3 = rp[3];
            uint32_t m1 = w0.x, m2 = w0.y;
            pmerge(m1, m2, w0.z, w0.w);
            pmerge(m1, m2, w1.x, w1.y);
            pmerge(m1, m2, w1.z, w1.w);
            pmerge(m1, m2, w2.x, w2.y);
            pmerge(m1, m2, w2.z, w2.w);
            pmerge(m1, m2, w3.x, w3.y);
            pmerge(m1, m2, w3.z, w3.w);
            uint32_t o1 = __shfl_xor_sync(0xffffffffu, m1, 1);
            uint32_t o2 = __shfl_xor_sync(0xffffffffu, m2, 1);
            pmerge(m1, m2, o1, o2);
            if (half == 0) {
                float f1 = dkey(m1), f2 = dkey(m2);
                sBI[row] = 511 - (int)(m1 & 0x1FFu);
                sBest[row] = f1;
                int flag = (f1 - f2 < TAU) ? 1 : 0;
                sFlg[row] = (unsigned char)flag;
                if (flag) {
                    int p = atomicAdd(sNF, 1);
                    sLst[p] = row;
                }
            }
        }
        __syncthreads();
        const int nflag = *sNF;
        const bool mine_flagged = sFlg[myrow] != 0;

        // ---- epilogue helper (z from smem zoff) ----
        auto do_epilogue = [&](int bi) {
            size_t rg = (size_t)tile * TROWS + myrow;
            if (myq == 0) {
                out[O_IDX + rg] = (float)bi;
                atomicAdd(&sCnt[bi], 1.0f);
            }
            const float4* er = (const float4*)(emb + (size_t)bi * CD + myq * 16);
            const float4* zr = (const float4*)(smem + zoff + myrow * 256 + myq * 64);
            float4* oq = (float4*)(out + O_ZQ + rg * CD + myq * 16);
            float* es = g_esum + (size_t)bi * CD + myq * 16;
#pragma unroll
            for (int i = 0; i < 4; i++) {
                float4 e = er[i], zf = zr[i];
                float d0 = e.x - zf.x, d1 = e.y - zf.y;
                float d2 = e.z - zf.z, d3 = e.w - zf.w;
                sse_acc += d0 * d0 + d1 * d1 + d2 * d2 + d3 * d3;
                oq[i] = make_float4(zf.x + d0, zf.y + d1, zf.z + d2, zf.w + d3);
                asm volatile("red.global.add.v4.f32 [%0], {%1,%2,%3,%4};"
                    :: "l"(es + i * 4), "f"(zf.x), "f"(zf.y), "f"(zf.z), "f"(zf.w)
                    : "memory");
            }
        };

        // ---- epilogue for unflagged rows (overlaps recheck below) ----
        if (!mine_flagged) do_epilogue(sBI[myrow]);

        // ---- candidate-pruned exact recheck (one warp per flagged row) ----
        if (nflag > 0) {
#pragma unroll 1
            for (int li = wid; li < nflag; li += 8) {
                int rowl = sLst[li];
                float thr = sBest[rowl] - TAU;
                float wb = -3.4e38f, wb2 = -3.4e38f; int wic = 0;
                if (lane < 16) {
                    uint2 v = sR2[rowl * 16 + lane];
                    wb = dkey(v.x); wb2 = dkey(v.y);
                    wic = 511 - (int)(v.x & 0x1FFu);
                }
                unsigned candm  = __ballot_sync(0xffffffffu, wb  >= thr);
                unsigned heavym = __ballot_sync(0xffffffffu, wb  >= thr && wb2 >= thr);
                unsigned lightm = candm & ~heavym;

                float4 f[16];
                {
                    const float4* zr = (const float4*)(smem + zoff + rowl * 256);
#pragma unroll
                    for (int i = 0; i < 16; i++) f[i] = zr[i];
                }
                float lb = -3.4e38f; int lj = NC;
                if (lightm & (1u << lane)) {
                    lb = exact_score(f, emb, sH, wic);
                    lj = wic;
                }
#pragma unroll 1
                while (heavym) {       // heavy block = 32 codes -> 1 scan
                    int c = __ffs(heavym) - 1; heavym &= heavym - 1;
                    int j = 32 * c + lane;
                    float sc = exact_score(f, emb, sH, j);
                    if (sc > lb || (sc == lb && j < lj)) { lb = sc; lj = j; }
                }
#pragma unroll
                for (int m = 16; m; m >>= 1) {
                    float ob = __shfl_xor_sync(0xffffffffu, lb, m);
                    int   oj = __shfl_xor_sync(0xffffffffu, lj, m);
                    if (ob > lb || (ob == lb && oj < lj)) { lb = ob; lj = oj; }
                }
                if (lane == 0) sBI[rowl] = lj;
            }
            __syncthreads();
            // ---- deferred epilogue for flagged rows ----
            if (mine_flagged) do_epilogue(sBI[myrow]);
        }

        cur = nxt;
        it++;
    }

    // ---- final merges ----
    __syncthreads();
#pragma unroll
    for (int i = 0; i < 2; i++) {
        float c = sCnt[tid + 256 * i];
        if (c != 0.0f) atomicAdd(&g_counts[tid + 256 * i], c);
    }
#pragma unroll
    for (int m = 16; m; m >>= 1) sse_acc += __shfl_xor_sync(0xffffffffu, sse_acc, m);
    if (lane == 0 && sse_acc != 0.0f) atomicAdd(&g_sse, sse_acc);
}

// ============================================================================
// Kernel 3: finalize EMA + loss. 64 blocks x 512 thr.
// ============================================================================
__global__ void vq_final(const float* __restrict__ cluster_size,
                         const float* __restrict__ embedding_avg,
                         float* __restrict__ out) {
    __shared__ float sncs[NC];
    __shared__ float sred[NC];
    const int t = threadIdx.x;
    const int b = blockIdx.x;

    float ncs = cluster_size[t] * 0.99f + 0.01f * g_counts[t];
    sncs[t] = ncs;
    sred[t] = ncs;
    if (b == 0) out[O_NCS + t] = ncs;
    __syncthreads();
#pragma unroll
    for (int o = NC / 2; o > 0; o >>= 1) {
        if (t < o) sred[t] += sred[t + o];
        __syncthreads();
    }
    const float n = sred[0];

    const int code = 8 * b + (t >> 6);
    const int k = t & 63;
    const size_t o = (size_t)code * CD + k;
    float ea = embedding_avg[o] * 0.99f + 0.01f * g_esum[o];
    out[O_NAVG + o] = ea;
    float cs = (sncs[code] + 1e-6f) / (n + (float)NC * 1e-6f);
    out[O_NEMB + o] = ea / cs;

    if (b == 0 && t == 0) out[O_LOSS] = 0.25f * g_sse / (float)NELEM;
}

// ============================================================================
extern "C" void kernel_launch(void* const* d_in, const int* in_sizes, int n_in,
                              void* d_out, int out_size) {
    const float* z    = (const float*)d_in[0];
    const float* emb  = (const float*)d_in[1];
    const float* csz  = (const float*)d_in[2];
    const float* eavg = (const float*)d_in[3];
    float* out = (float*)d_out;

    cudaFuncSetAttribute(vq_main, cudaFuncAttributeMaxDynamicSharedMemorySize, SMEM_SZ);
    vq_init<<<256, 128>>>(emb);
    vq_nop1<<<1, 1>>>();
    vq_nop2<<<1, 1>>>();
    vq_main<<<GRID, 256, SMEM_SZ>>>(z, emb, out);
    vq_final<<<64, NC>>>(csz, eavg, out);
}